// round 12
// baseline (speedup 1.0000x reference)
#include <cuda_runtime.h>

#define NB 16
#define SECL 16
#define WORDL 256
#define SLEN 4096
#define DIM 1024
#define FSZ 2
#define GATH (FSZ*WORDL)   // 512
#define NPART 64           // context partials (one per 8-row chunk)
#define KSPLIT 8           // k1 K-dimension split

// ---------------- scratch (device globals; no allocation) ----------------
__device__ float g_decpart[KSPLIT*NB*DIM];  // k1 partial dec features (bias in split 0)
__device__ float g_scores[NB*GATH];
__device__ float g_ctxpart[NPART*NB*DIM];   // 4 MB

// accurate tanh: 1 - 2/(e^{2x}+1), ex2/rcp MUFU (~1e-7 abs error)
__device__ __forceinline__ float fast_tanh(float x) {
    float e;
    asm("ex2.approx.f32 %0, %1;" : "=f"(e) : "f"(x * 2.8853900817779268f)); // 2*log2(e)
    float r;
    asm("rcp.approx.f32 %0, %1;" : "=f"(r) : "f"(e + 1.0f));
    return 1.0f - 2.0f * r;
}

// top-2 of focus[b] (jax first-occurrence tie rule); run by ONE thread
__device__ __forceinline__ void top2_focus(const float* __restrict__ focus, int b,
                                           int& i0, int& i1, float& v0, float& v1) {
    const float* f = focus + b*SECL;
    v0 = -__int_as_float(0x7f800000); i0 = 0;
#pragma unroll
    for (int j = 0; j < SECL; j++) { float x = __ldg(&f[j]); if (x > v0) { v0 = x; i0 = j; } }
    v1 = -__int_as_float(0x7f800000); i1 = 0;
#pragma unroll
    for (int j = 0; j < SECL; j++) {
        if (j == i0) continue;
        float x = __ldg(&f[j]); if (x > v1) { v1 = x; i1 = j; }
    }
}

// ---------------- K1: dec_feature partials, K split 8-way ----------------
// grid 1024 = 128 d-groups * 8 k-splits; warp owns 1 dim, 128 K-floats (1 float4/lane).
__global__ __launch_bounds__(256) void k1_decproj(const float* __restrict__ h,
                                                  const float* __restrict__ W,
                                                  const float* __restrict__ bvec) {
    int warp = threadIdx.x >> 5;
    int lane = threadIdx.x & 31;
    int dg = blockIdx.x >> 3;          // 0..127
    int ks = blockIdx.x & 7;           // 0..7
    int d  = dg*8 + warp;
    int k0 = ks*32;                    // float4 offset of this K eighth
    float4 w = __ldg((const float4*)(W + (size_t)d*DIM) + k0 + lane);
    const float4* h4 = (const float4*)h + k0 + lane;
    float acc[NB];
#pragma unroll
    for (int b = 0; b < NB; b++) {
        float4 hb = __ldg(h4 + b*256);
        acc[b] = fmaf(w.x, hb.x, fmaf(w.y, hb.y, fmaf(w.z, hb.z, w.w*hb.w)));
    }
#pragma unroll
    for (int b = 0; b < NB; b++) {
#pragma unroll
        for (int o = 16; o > 0; o >>= 1)
            acc[b] += __shfl_xor_sync(0xffffffffu, acc[b], o);
    }
    if (lane == 0) {
        float bd = (ks == 0) ? bvec[d] : 0.f;
#pragma unroll
        for (int b = 0; b < NB; b++)
            g_decpart[(ks*NB + b)*DIM + d] = acc[b] + bd;
    }
}

// ---------------- K3 fused: scores + unnormalized weighted context partials ----------------
// 1024 blocks * 256 threads. Block = 8 consecutive rows of one (b, section-chunk).
__global__ __launch_bounds__(256) void k3_fused(const float* __restrict__ enc_feature,
                                                const float* __restrict__ enc_output,
                                                const float* __restrict__ enc_mask,
                                                const float* __restrict__ coverage,
                                                const float* __restrict__ vvec,
                                                const float* __restrict__ w_cov,
                                                const float* __restrict__ focus) {
    __shared__ float sh_ps[8][8];   // [warp][row]
    __shared__ float sh_w[8];
    __shared__ float sh_m[8];
    __shared__ float sh_cov[8];
    __shared__ int   sh_sec;
    int id = blockIdx.x;
    int b  = id >> 6;
    int c  = id & 63;              // chunk within batch
    int f  = c >> 5;
    int w0 = (c & 31) * 8;         // word offset within section
    int warp = threadIdx.x >> 5;
    int lane = threadIdx.x & 31;
    if (threadIdx.x == 0) {
        int i0, i1; float v0, v1;
        top2_focus(focus, b, i0, i1, v0, v1);
        sh_sec = f ? i1 : i0;
    }
    __syncthreads();
    int srow = b*SLEN + sh_sec*WORDL + w0;     // global row index of row 0
    if (threadIdx.x < 8) {
        sh_m[threadIdx.x]   = enc_mask[srow + threadIdx.x];
        sh_cov[threadIdx.x] = coverage[srow + threadIdx.x];
    }
    __syncthreads();

    int sl = warp*32 + lane;                   // float4 index within dim
    const float4* efp = (const float4*)enc_feature + (size_t)srow*(DIM/4) + sl;
    float4 e0 = __ldg(efp + 0*(DIM/4));
    float4 e1 = __ldg(efp + 1*(DIM/4));
    float4 e2 = __ldg(efp + 2*(DIM/4));
    float4 e3 = __ldg(efp + 3*(DIM/4));
    float4 e4 = __ldg(efp + 4*(DIM/4));
    float4 e5 = __ldg(efp + 5*(DIM/4));
    float4 e6 = __ldg(efp + 6*(DIM/4));
    float4 e7 = __ldg(efp + 7*(DIM/4));
    // dec feature = sum of 8 K-split partials (bias folded into split 0)
    const float4* dp = (const float4*)g_decpart + b*(DIM/4) + sl;
    float4 d0 = dp[0*(NB*DIM/4)];
    float4 d1 = dp[1*(NB*DIM/4)];
    float4 d2 = dp[2*(NB*DIM/4)];
    float4 d3 = dp[3*(NB*DIM/4)];
    float4 d4 = dp[4*(NB*DIM/4)];
    float4 d5 = dp[5*(NB*DIM/4)];
    float4 d6 = dp[6*(NB*DIM/4)];
    float4 d7 = dp[7*(NB*DIM/4)];
    float4 dd = make_float4(((d0.x+d1.x)+(d2.x+d3.x)) + ((d4.x+d5.x)+(d6.x+d7.x)),
                            ((d0.y+d1.y)+(d2.y+d3.y)) + ((d4.y+d5.y)+(d6.y+d7.y)),
                            ((d0.z+d1.z)+(d2.z+d3.z)) + ((d4.z+d5.z)+(d6.z+d7.z)),
                            ((d0.w+d1.w)+(d2.w+d3.w)) + ((d4.w+d5.w)+(d6.w+d7.w)));
    float4 vv = __ldg((const float4*)vvec  + sl);
    float4 wc = __ldg((const float4*)w_cov + sl);
    float ps[8];
#define K3ROW(EV, R) { float cv = sh_cov[R]; \
        ps[R] = vv.x * fast_tanh(fmaf(cv, wc.x, EV.x + dd.x)) \
              + vv.y * fast_tanh(fmaf(cv, wc.y, EV.y + dd.y)) \
              + vv.z * fast_tanh(fmaf(cv, wc.z, EV.z + dd.z)) \
              + vv.w * fast_tanh(fmaf(cv, wc.w, EV.w + dd.w)); }
    K3ROW(e0, 0) K3ROW(e1, 1) K3ROW(e2, 2) K3ROW(e3, 3)
    K3ROW(e4, 4) K3ROW(e5, 5) K3ROW(e6, 6) K3ROW(e7, 7)
#undef K3ROW
#pragma unroll
    for (int r = 0; r < 8; r++) {
#pragma unroll
        for (int o = 16; o > 0; o >>= 1)
            ps[r] += __shfl_xor_sync(0xffffffffu, ps[r], o);
    }
    if (lane == 0) {
#pragma unroll
        for (int r = 0; r < 8; r++) sh_ps[warp][r] = ps[r];
    }
    __syncthreads();
    if (threadIdx.x < 8) {
        int r = threadIdx.x;
        float sc = ((sh_ps[0][r] + sh_ps[1][r]) + (sh_ps[2][r] + sh_ps[3][r]))
                 + ((sh_ps[4][r] + sh_ps[5][r]) + (sh_ps[6][r] + sh_ps[7][r]));
        g_scores[b*GATH + f*WORDL + w0 + r] = sc;
        sh_w[r] = __expf(sc) * sh_m[r];        // unnormalized weight
    }
    __syncthreads();

    const float4* eop = (const float4*)enc_output + (size_t)srow*(DIM/4) + sl;
    float4 r0 = __ldg(eop + 0*(DIM/4));
    float4 r1 = __ldg(eop + 1*(DIM/4));
    float4 r2 = __ldg(eop + 2*(DIM/4));
    float4 r3 = __ldg(eop + 3*(DIM/4));
    float4 r4 = __ldg(eop + 4*(DIM/4));
    float4 r5 = __ldg(eop + 5*(DIM/4));
    float4 r6 = __ldg(eop + 6*(DIM/4));
    float4 r7 = __ldg(eop + 7*(DIM/4));
    float c0 = sh_w[0], c1 = sh_w[1], c2 = sh_w[2], c3 = sh_w[3];
    float c4 = sh_w[4], c5 = sh_w[5], c6 = sh_w[6], c7 = sh_w[7];
    float4 s;
    s.x = (fmaf(c0,r0.x, c1*r1.x) + fmaf(c2,r2.x, c3*r3.x))
        + (fmaf(c4,r4.x, c5*r5.x) + fmaf(c6,r6.x, c7*r7.x));
    s.y = (fmaf(c0,r0.y, c1*r1.y) + fmaf(c2,r2.y, c3*r3.y))
        + (fmaf(c4,r4.y, c5*r5.y) + fmaf(c6,r6.y, c7*r7.y));
    s.z = (fmaf(c0,r0.z, c1*r1.z) + fmaf(c2,r2.z, c3*r3.z))
        + (fmaf(c4,r4.z, c5*r5.z) + fmaf(c6,r6.z, c7*r7.z));
    s.w = (fmaf(c0,r0.w, c1*r1.w) + fmaf(c2,r2.w, c3*r3.w))
        + (fmaf(c4,r4.w, c5*r5.w) + fmaf(c6,r6.w, c7*r7.w));
    *((float4*)(g_ctxpart + ((size_t)(c*NB + b))*DIM) + sl) = s;
}

// ---------------- block reduce (256 threads, 8 warps) ----------------
__device__ __forceinline__ float blkred256(float v, float* red, bool is_max) {
#pragma unroll
    for (int o = 16; o > 0; o >>= 1) {
        float t = __shfl_xor_sync(0xffffffffu, v, o);
        v = is_max ? fmaxf(v, t) : (v + t);
    }
    __syncthreads();
    if ((threadIdx.x & 31) == 0) red[threadIdx.x >> 5] = v;
    __syncthreads();
    if (threadIdx.x < 32) {
        float x = (threadIdx.x < 8) ? red[threadIdx.x]
                                    : (is_max ? -__int_as_float(0x7f800000) : 0.f);
#pragma unroll
        for (int o = 4; o > 0; o >>= 1) {
            float t = __shfl_xor_sync(0xffffffffu, x, o);
            x = is_max ? fmaxf(x, t) : (x + t);
        }
        if (threadIdx.x == 0) red[0] = x;
    }
    __syncthreads();
    return red[0];
}

// ---------------- K6: fused epilogue — softmax recompute + scaled combine + scatter ----------------
__global__ __launch_bounds__(256) void k6_epilogue(const float* __restrict__ enc_mask,
                                                   const float* __restrict__ coverage,
                                                   const float* __restrict__ focus,
                                                   float* __restrict__ out) {
    __shared__ float red[8];
    __shared__ int   sh_i[2];
    __shared__ float sh_v[2];
    bool is_comb = blockIdx.x < 128;
    int b = is_comb ? (blockIdx.x >> 3) : ((blockIdx.x - 128) >> 2);
    int tid = threadIdx.x;
    if (tid == 0) {
        int i0, i1; float v0, v1;
        top2_focus(focus, b, i0, i1, v0, v1);
        sh_i[0] = i0; sh_i[1] = i1; sh_v[0] = v0; sh_v[1] = v1;
    }
    __syncthreads();
    int i0 = sh_i[0], i1 = sh_i[1];
    float v0 = sh_v[0], v1 = sh_v[1];
    float sc0 = g_scores[b*GATH + tid];
    float sc1 = g_scores[b*GATH + WORDL + tid];
    float m0  = __ldg(&enc_mask[b*SLEN + i0*WORDL + tid]);
    float m1  = __ldg(&enc_mask[b*SLEN + i1*WORDL + tid]);
    float mx  = blkred256(fmaxf(sc0, sc1), red, true);
    float e0  = __expf(sc0 - mx) * m0;
    float e1  = __expf(sc1 - mx) * m1;
    float S   = blkred256(fmaf(v0, e0, v1*e1), red, false);

    if (is_comb) {
        __shared__ float4 shc[8][32];
        float emx = __expf(-mx);
        float scale0 = v0 * emx / S;
        float scale1 = v1 * emx / S;
        int o = tid & 31;
        int g = tid >> 5;
        int i = b*256 + (blockIdx.x & 7)*32 + o;
        const float4* cp = (const float4*)g_ctxpart + i;
        float4 t0 = cp[(size_t)(g*8 + 0)*(NB*DIM/4)];
        float4 t1 = cp[(size_t)(g*8 + 1)*(NB*DIM/4)];
        float4 t2 = cp[(size_t)(g*8 + 2)*(NB*DIM/4)];
        float4 t3 = cp[(size_t)(g*8 + 3)*(NB*DIM/4)];
        float4 t4 = cp[(size_t)(g*8 + 4)*(NB*DIM/4)];
        float4 t5 = cp[(size_t)(g*8 + 5)*(NB*DIM/4)];
        float4 t6 = cp[(size_t)(g*8 + 6)*(NB*DIM/4)];
        float4 t7 = cp[(size_t)(g*8 + 7)*(NB*DIM/4)];
        float sc = (g < 4) ? scale0 : scale1;
        shc[g][o] = make_float4(
            sc*(((t0.x+t1.x)+(t2.x+t3.x)) + ((t4.x+t5.x)+(t6.x+t7.x))),
            sc*(((t0.y+t1.y)+(t2.y+t3.y)) + ((t4.y+t5.y)+(t6.y+t7.y))),
            sc*(((t0.z+t1.z)+(t2.z+t3.z)) + ((t4.z+t5.z)+(t6.z+t7.z))),
            sc*(((t0.w+t1.w)+(t2.w+t3.w)) + ((t4.w+t5.w)+(t6.w+t7.w))));
        __syncthreads();
        if (tid < 32) {
            float4 a = shc[0][tid], b4 = shc[1][tid], c4 = shc[2][tid], d4 = shc[3][tid];
            float4 e4 = shc[4][tid], f4 = shc[5][tid], g4 = shc[6][tid], h4 = shc[7][tid];
            int ii = b*256 + (blockIdx.x & 7)*32 + tid;
            ((float4*)out)[ii] = make_float4(
                ((a.x+b4.x)+(c4.x+d4.x)) + ((e4.x+f4.x)+(g4.x+h4.x)),
                ((a.y+b4.y)+(c4.y+d4.y)) + ((e4.y+f4.y)+(g4.y+h4.y)),
                ((a.z+b4.z)+(c4.z+d4.z)) + ((e4.z+f4.z)+(g4.z+h4.z)),
                ((a.w+b4.w)+(c4.w+d4.w)) + ((e4.w+f4.w)+(g4.w+h4.w)));
        }
    } else {
        int gb = blockIdx.x - 128;
        int p4 = (gb & 3)*256 + tid;
        int pos = p4 << 2;
        int si = pos >> 8;
        int w  = pos & 255;
        float4 av = make_float4(0.f, 0.f, 0.f, 0.f);
        float4 m4 = __ldg((const float4*)(enc_mask + b*SLEN) + p4);
        if (si == i0) {
            float4 s4 = *(const float4*)(g_scores + b*GATH + w);
            float k = v0 / S;
            av = make_float4(k*__expf(s4.x - mx)*m4.x, k*__expf(s4.y - mx)*m4.y,
                             k*__expf(s4.z - mx)*m4.z, k*__expf(s4.w - mx)*m4.w);
        } else if (si == i1) {
            float4 s4 = *(const float4*)(g_scores + b*GATH + WORDL + w);
            float k = v1 / S;
            av = make_float4(k*__expf(s4.x - mx)*m4.x, k*__expf(s4.y - mx)*m4.y,
                             k*__expf(s4.z - mx)*m4.z, k*__expf(s4.w - mx)*m4.w);
        }
        float4 cv = __ldg((const float4*)(coverage + b*SLEN) + p4);
        float4* oa = (float4*)(out + NB*DIM + b*SLEN);
        float4* oc = (float4*)(out + NB*DIM + NB*SLEN + b*SLEN);
        oa[p4] = av;
        oc[p4] = make_float4(cv.x + av.x, cv.y + av.y, cv.z + av.z, cv.w + av.w);
    }
}

extern "C" void kernel_launch(void* const* d_in, const int* in_sizes, int n_in,
                              void* d_out, int out_size) {
    const float* dec_hidden  = (const float*)d_in[0];
    const float* enc_output  = (const float*)d_in[1];
    const float* enc_feature = (const float*)d_in[2];
    const float* enc_mask    = (const float*)d_in[3];
    // d_in[4] = sec_attn (unused by reference)
    const float* coverage    = (const float*)d_in[5];
    const float* focus       = (const float*)d_in[6];
    const float* W_dec       = (const float*)d_in[7];
    const float* b_dec       = (const float*)d_in[8];
    const float* vvec        = (const float*)d_in[9];
    const float* w_cov       = (const float*)d_in[10];
    float* out = (float*)d_out;

    k1_decproj<<<1024, 256>>>(dec_hidden, W_dec, b_dec);
    k3_fused<<<1024, 256>>>(enc_feature, enc_output, enc_mask, coverage,
                            vvec, w_cov, focus);
    k6_epilogue<<<192, 256>>>(enc_mask, coverage, focus, out);
}

// round 13
// speedup vs baseline: 1.1761x; 1.1761x over previous
#include <cuda_runtime.h>

#define NB 16
#define SECL 16
#define WORDL 256
#define SLEN 4096
#define DIM 1024
#define FSZ 2
#define GATH (FSZ*WORDL)   // 512
#define NPART 64           // context partials (one per 8-row chunk)
#define KSPLIT 4           // k1 K-dimension split

// ---------------- scratch (device globals; no allocation) ----------------
__device__ float g_decpart[KSPLIT*NB*DIM];  // k1 partial dec features (bias in split 0)
__device__ float g_scores[NB*GATH];
__device__ float g_ctxpart[NPART*NB*DIM];   // 4 MB

// accurate tanh: 1 - 2/(e^{2x}+1), ex2/rcp MUFU (~1e-7 abs error)
__device__ __forceinline__ float fast_tanh(float x) {
    float e;
    asm("ex2.approx.f32 %0, %1;" : "=f"(e) : "f"(x * 2.8853900817779268f)); // 2*log2(e)
    float r;
    asm("rcp.approx.f32 %0, %1;" : "=f"(r) : "f"(e + 1.0f));
    return 1.0f - 2.0f * r;
}

// top-2 of focus[b] (jax first-occurrence tie rule); run by ONE thread
__device__ __forceinline__ void top2_focus(const float* __restrict__ focus, int b,
                                           int& i0, int& i1, float& v0, float& v1) {
    const float* f = focus + b*SECL;
    v0 = -__int_as_float(0x7f800000); i0 = 0;
#pragma unroll
    for (int j = 0; j < SECL; j++) { float x = __ldg(&f[j]); if (x > v0) { v0 = x; i0 = j; } }
    v1 = -__int_as_float(0x7f800000); i1 = 0;
#pragma unroll
    for (int j = 0; j < SECL; j++) {
        if (j == i0) continue;
        float x = __ldg(&f[j]); if (x > v1) { v1 = x; i1 = j; }
    }
}

// ---------------- K1: dec_feature partials, K split 4-way, merge-tree reduce ----------------
// grid 512 = 128 d-groups * 4 k-splits; warp owns 1 dim, 256 K-floats (2 float4/lane).
__global__ __launch_bounds__(256) void k1_decproj(const float* __restrict__ h,
                                                  const float* __restrict__ W,
                                                  const float* __restrict__ bvec) {
    int warp = threadIdx.x >> 5;
    int lane = threadIdx.x & 31;
    int dg = blockIdx.x >> 2;          // 0..127
    int ks = blockIdx.x & 3;           // 0..3
    int d  = dg*8 + warp;
    int k0 = ks*64;                    // float4 offset of this K quarter
    const float4* Wd = (const float4*)(W + (size_t)d*DIM) + k0 + lane;
    const float4* h4 = (const float4*)h + k0 + lane;
    float4 w0 = __ldg(Wd);
    float4 w1 = __ldg(Wd + 32);
    float acc[NB];
#pragma unroll
    for (int b = 0; b < NB; b++) {
        float4 a = __ldg(h4 + b*256);
        float4 c = __ldg(h4 + b*256 + 32);
        acc[b] = fmaf(w0.x,a.x, fmaf(w0.y,a.y, fmaf(w0.z,a.z, fmaf(w0.w,a.w,
                 fmaf(w1.x,c.x, fmaf(w1.y,c.y, fmaf(w1.z,c.z, w1.w*c.w)))))));
    }
    // merge-tree reduction: 16 accs -> 1 per lane (16 SHFL total)
#pragma unroll
    for (int i = 0; i < 8; i++) {
        float x = (lane & 16) ? acc[i] : acc[i+8];
        float y = __shfl_xor_sync(0xffffffffu, x, 16);
        acc[i] = ((lane & 16) ? acc[i+8] : acc[i]) + y;
    }
#pragma unroll
    for (int i = 0; i < 4; i++) {
        float x = (lane & 8) ? acc[i] : acc[i+4];
        float y = __shfl_xor_sync(0xffffffffu, x, 8);
        acc[i] = ((lane & 8) ? acc[i+4] : acc[i]) + y;
    }
#pragma unroll
    for (int i = 0; i < 2; i++) {
        float x = (lane & 4) ? acc[i] : acc[i+2];
        float y = __shfl_xor_sync(0xffffffffu, x, 4);
        acc[i] = ((lane & 4) ? acc[i+2] : acc[i]) + y;
    }
    {
        float x = (lane & 2) ? acc[0] : acc[1];
        float y = __shfl_xor_sync(0xffffffffu, x, 2);
        acc[0] = ((lane & 2) ? acc[1] : acc[0]) + y;
    }
    acc[0] += __shfl_xor_sync(0xffffffffu, acc[0], 1);
    // even lane holds full sum for batch b(lane)
    int b = ((lane >> 4) & 1)*8 + ((lane >> 3) & 1)*4 + ((lane >> 2) & 1)*2 + ((lane >> 1) & 1);
    if ((lane & 1) == 0) {
        float bd = (ks == 0) ? __ldg(&bvec[d]) : 0.f;
        g_decpart[(ks*NB + b)*DIM + d] = acc[0] + bd;
    }
}

// ---------------- K3 fused: scores + unnormalized weighted context partials ----------------
// 1024 blocks * 256 threads. Block = 8 consecutive rows of one (b, section-chunk).
__global__ __launch_bounds__(256) void k3_fused(const float* __restrict__ enc_feature,
                                                const float* __restrict__ enc_output,
                                                const float* __restrict__ enc_mask,
                                                const float* __restrict__ coverage,
                                                const float* __restrict__ vvec,
                                                const float* __restrict__ w_cov,
                                                const float* __restrict__ focus) {
    __shared__ float sh_ps[8][8];   // [warp][row]
    __shared__ float sh_w[8];
    __shared__ float sh_m[8];
    __shared__ float sh_cov[8];
    __shared__ int   sh_sec;
    int id = blockIdx.x;
    int b  = id >> 6;
    int c  = id & 63;              // chunk within batch
    int f  = c >> 5;
    int w0 = (c & 31) * 8;         // word offset within section
    int warp = threadIdx.x >> 5;
    int lane = threadIdx.x & 31;
    if (threadIdx.x == 0) {
        int i0, i1; float v0, v1;
        top2_focus(focus, b, i0, i1, v0, v1);
        sh_sec = f ? i1 : i0;
    }
    __syncthreads();
    int srow = b*SLEN + sh_sec*WORDL + w0;     // global row index of row 0
    if (threadIdx.x < 8) {
        sh_m[threadIdx.x]   = enc_mask[srow + threadIdx.x];
        sh_cov[threadIdx.x] = coverage[srow + threadIdx.x];
    }
    __syncthreads();

    int sl = warp*32 + lane;                   // float4 index within dim
    const float4* efp = (const float4*)enc_feature + (size_t)srow*(DIM/4) + sl;
    float4 e0 = __ldg(efp + 0*(DIM/4));
    float4 e1 = __ldg(efp + 1*(DIM/4));
    float4 e2 = __ldg(efp + 2*(DIM/4));
    float4 e3 = __ldg(efp + 3*(DIM/4));
    float4 e4 = __ldg(efp + 4*(DIM/4));
    float4 e5 = __ldg(efp + 5*(DIM/4));
    float4 e6 = __ldg(efp + 6*(DIM/4));
    float4 e7 = __ldg(efp + 7*(DIM/4));
    // dec feature = sum of 4 K-split partials (bias folded into split 0)
    const float4* dp = (const float4*)g_decpart + b*(DIM/4) + sl;
    float4 d0 = dp[0*(NB*DIM/4)];
    float4 d1 = dp[1*(NB*DIM/4)];
    float4 d2 = dp[2*(NB*DIM/4)];
    float4 d3 = dp[3*(NB*DIM/4)];
    float4 dd = make_float4((d0.x+d1.x)+(d2.x+d3.x), (d0.y+d1.y)+(d2.y+d3.y),
                            (d0.z+d1.z)+(d2.z+d3.z), (d0.w+d1.w)+(d2.w+d3.w));
    float4 vv = __ldg((const float4*)vvec  + sl);
    float4 wc = __ldg((const float4*)w_cov + sl);
    float ps[8];
#define K3ROW(EV, R) { float cv = sh_cov[R]; \
        ps[R] = vv.x * fast_tanh(fmaf(cv, wc.x, EV.x + dd.x)) \
              + vv.y * fast_tanh(fmaf(cv, wc.y, EV.y + dd.y)) \
              + vv.z * fast_tanh(fmaf(cv, wc.z, EV.z + dd.z)) \
              + vv.w * fast_tanh(fmaf(cv, wc.w, EV.w + dd.w)); }
    K3ROW(e0, 0) K3ROW(e1, 1) K3ROW(e2, 2) K3ROW(e3, 3)
    K3ROW(e4, 4) K3ROW(e5, 5) K3ROW(e6, 6) K3ROW(e7, 7)
#undef K3ROW
#pragma unroll
    for (int r = 0; r < 8; r++) {
#pragma unroll
        for (int o = 16; o > 0; o >>= 1)
            ps[r] += __shfl_xor_sync(0xffffffffu, ps[r], o);
    }
    if (lane == 0) {
#pragma unroll
        for (int r = 0; r < 8; r++) sh_ps[warp][r] = ps[r];
    }
    __syncthreads();
    if (threadIdx.x < 8) {
        int r = threadIdx.x;
        float sc = ((sh_ps[0][r] + sh_ps[1][r]) + (sh_ps[2][r] + sh_ps[3][r]))
                 + ((sh_ps[4][r] + sh_ps[5][r]) + (sh_ps[6][r] + sh_ps[7][r]));
        g_scores[b*GATH + f*WORDL + w0 + r] = sc;
        sh_w[r] = __expf(sc) * sh_m[r];        // unnormalized weight
    }
    __syncthreads();

    const float4* eop = (const float4*)enc_output + (size_t)srow*(DIM/4) + sl;
    float4 r0 = __ldg(eop + 0*(DIM/4));
    float4 r1 = __ldg(eop + 1*(DIM/4));
    float4 r2 = __ldg(eop + 2*(DIM/4));
    float4 r3 = __ldg(eop + 3*(DIM/4));
    float4 r4 = __ldg(eop + 4*(DIM/4));
    float4 r5 = __ldg(eop + 5*(DIM/4));
    float4 r6 = __ldg(eop + 6*(DIM/4));
    float4 r7 = __ldg(eop + 7*(DIM/4));
    float c0 = sh_w[0], c1 = sh_w[1], c2 = sh_w[2], c3 = sh_w[3];
    float c4 = sh_w[4], c5 = sh_w[5], c6 = sh_w[6], c7 = sh_w[7];
    float4 s;
    s.x = (fmaf(c0,r0.x, c1*r1.x) + fmaf(c2,r2.x, c3*r3.x))
        + (fmaf(c4,r4.x, c5*r5.x) + fmaf(c6,r6.x, c7*r7.x));
    s.y = (fmaf(c0,r0.y, c1*r1.y) + fmaf(c2,r2.y, c3*r3.y))
        + (fmaf(c4,r4.y, c5*r5.y) + fmaf(c6,r6.y, c7*r7.y));
    s.z = (fmaf(c0,r0.z, c1*r1.z) + fmaf(c2,r2.z, c3*r3.z))
        + (fmaf(c4,r4.z, c5*r5.z) + fmaf(c6,r6.z, c7*r7.z));
    s.w = (fmaf(c0,r0.w, c1*r1.w) + fmaf(c2,r2.w, c3*r3.w))
        + (fmaf(c4,r4.w, c5*r5.w) + fmaf(c6,r6.w, c7*r7.w));
    *((float4*)(g_ctxpart + ((size_t)(c*NB + b))*DIM) + sl) = s;
}

// ---------------- block reduce (256 threads, 8 warps) ----------------
__device__ __forceinline__ float blkred256(float v, float* red, bool is_max) {
#pragma unroll
    for (int o = 16; o > 0; o >>= 1) {
        float t = __shfl_xor_sync(0xffffffffu, v, o);
        v = is_max ? fmaxf(v, t) : (v + t);
    }
    __syncthreads();
    if ((threadIdx.x & 31) == 0) red[threadIdx.x >> 5] = v;
    __syncthreads();
    if (threadIdx.x < 32) {
        float x = (threadIdx.x < 8) ? red[threadIdx.x]
                                    : (is_max ? -__int_as_float(0x7f800000) : 0.f);
#pragma unroll
        for (int o = 4; o > 0; o >>= 1) {
            float t = __shfl_xor_sync(0xffffffffu, x, o);
            x = is_max ? fmaxf(x, t) : (x + t);
        }
        if (threadIdx.x == 0) red[0] = x;
    }
    __syncthreads();
    return red[0];
}

// ---------------- K6: fused epilogue — softmax recompute + scaled combine + scatter ----------------
__global__ __launch_bounds__(256) void k6_epilogue(const float* __restrict__ enc_mask,
                                                   const float* __restrict__ coverage,
                                                   const float* __restrict__ focus,
                                                   float* __restrict__ out) {
    __shared__ float red[8];
    __shared__ int   sh_i[2];
    __shared__ float sh_v[2];
    bool is_comb = blockIdx.x < 128;
    int b = is_comb ? (blockIdx.x >> 3) : ((blockIdx.x - 128) >> 2);
    int tid = threadIdx.x;
    if (tid == 0) {
        int i0, i1; float v0, v1;
        top2_focus(focus, b, i0, i1, v0, v1);
        sh_i[0] = i0; sh_i[1] = i1; sh_v[0] = v0; sh_v[1] = v1;
    }
    __syncthreads();
    int i0 = sh_i[0], i1 = sh_i[1];
    float v0 = sh_v[0], v1 = sh_v[1];
    float sc0 = g_scores[b*GATH + tid];
    float sc1 = g_scores[b*GATH + WORDL + tid];
    float m0  = __ldg(&enc_mask[b*SLEN + i0*WORDL + tid]);
    float m1  = __ldg(&enc_mask[b*SLEN + i1*WORDL + tid]);
    float mx  = blkred256(fmaxf(sc0, sc1), red, true);
    float e0  = __expf(sc0 - mx) * m0;
    float e1  = __expf(sc1 - mx) * m1;
    float S   = blkred256(fmaf(v0, e0, v1*e1), red, false);

    if (is_comb) {
        __shared__ float4 shc[8][32];
        float emx = __expf(-mx);
        float scale0 = v0 * emx / S;
        float scale1 = v1 * emx / S;
        int o = tid & 31;
        int g = tid >> 5;
        int i = b*256 + (blockIdx.x & 7)*32 + o;
        const float4* cp = (const float4*)g_ctxpart + i;
        float4 t0 = cp[(size_t)(g*8 + 0)*(NB*DIM/4)];
        float4 t1 = cp[(size_t)(g*8 + 1)*(NB*DIM/4)];
        float4 t2 = cp[(size_t)(g*8 + 2)*(NB*DIM/4)];
        float4 t3 = cp[(size_t)(g*8 + 3)*(NB*DIM/4)];
        float4 t4 = cp[(size_t)(g*8 + 4)*(NB*DIM/4)];
        float4 t5 = cp[(size_t)(g*8 + 5)*(NB*DIM/4)];
        float4 t6 = cp[(size_t)(g*8 + 6)*(NB*DIM/4)];
        float4 t7 = cp[(size_t)(g*8 + 7)*(NB*DIM/4)];
        float sc = (g < 4) ? scale0 : scale1;
        shc[g][o] = make_float4(
            sc*(((t0.x+t1.x)+(t2.x+t3.x)) + ((t4.x+t5.x)+(t6.x+t7.x))),
            sc*(((t0.y+t1.y)+(t2.y+t3.y)) + ((t4.y+t5.y)+(t6.y+t7.y))),
            sc*(((t0.z+t1.z)+(t2.z+t3.z)) + ((t4.z+t5.z)+(t6.z+t7.z))),
            sc*(((t0.w+t1.w)+(t2.w+t3.w)) + ((t4.w+t5.w)+(t6.w+t7.w))));
        __syncthreads();
        if (tid < 32) {
            float4 a = shc[0][tid], b4 = shc[1][tid], c4 = shc[2][tid], d4 = shc[3][tid];
            float4 e4 = shc[4][tid], f4 = shc[5][tid], g4 = shc[6][tid], h4 = shc[7][tid];
            int ii = b*256 + (blockIdx.x & 7)*32 + tid;
            ((float4*)out)[ii] = make_float4(
                ((a.x+b4.x)+(c4.x+d4.x)) + ((e4.x+f4.x)+(g4.x+h4.x)),
                ((a.y+b4.y)+(c4.y+d4.y)) + ((e4.y+f4.y)+(g4.y+h4.y)),
                ((a.z+b4.z)+(c4.z+d4.z)) + ((e4.z+f4.z)+(g4.z+h4.z)),
                ((a.w+b4.w)+(c4.w+d4.w)) + ((e4.w+f4.w)+(g4.w+h4.w)));
        }
    } else {
        int gb = blockIdx.x - 128;
        int p4 = (gb & 3)*256 + tid;
        int pos = p4 << 2;
        int si = pos >> 8;
        int w  = pos & 255;
        float4 av = make_float4(0.f, 0.f, 0.f, 0.f);
        float4 m4 = __ldg((const float4*)(enc_mask + b*SLEN) + p4);
        if (si == i0) {
            float4 s4 = *(const float4*)(g_scores + b*GATH + w);
            float k = v0 / S;
            av = make_float4(k*__expf(s4.x - mx)*m4.x, k*__expf(s4.y - mx)*m4.y,
                             k*__expf(s4.z - mx)*m4.z, k*__expf(s4.w - mx)*m4.w);
        } else if (si == i1) {
            float4 s4 = *(const float4*)(g_scores + b*GATH + WORDL + w);
            float k = v1 / S;
            av = make_float4(k*__expf(s4.x - mx)*m4.x, k*__expf(s4.y - mx)*m4.y,
                             k*__expf(s4.z - mx)*m4.z, k*__expf(s4.w - mx)*m4.w);
        }
        float4 cv = __ldg((const float4*)(coverage + b*SLEN) + p4);
        float4* oa = (float4*)(out + NB*DIM + b*SLEN);
        float4* oc = (float4*)(out + NB*DIM + NB*SLEN + b*SLEN);
        oa[p4] = av;
        oc[p4] = make_float4(cv.x + av.x, cv.y + av.y, cv.z + av.z, cv.w + av.w);
    }
}

extern "C" void kernel_launch(void* const* d_in, const int* in_sizes, int n_in,
                              void* d_out, int out_size) {
    const float* dec_hidden  = (const float*)d_in[0];
    const float* enc_output  = (const float*)d_in[1];
    const float* enc_feature = (const float*)d_in[2];
    const float* enc_mask    = (const float*)d_in[3];
    // d_in[4] = sec_attn (unused by reference)
    const float* coverage    = (const float*)d_in[5];
    const float* focus       = (const float*)d_in[6];
    const float* W_dec       = (const float*)d_in[7];
    const float* b_dec       = (const float*)d_in[8];
    const float* vvec        = (const float*)d_in[9];
    const float* w_cov       = (const float*)d_in[10];
    float* out = (float*)d_out;

    k1_decproj<<<512, 256>>>(dec_hidden, W_dec, b_dec);
    k3_fused<<<1024, 256>>>(enc_feature, enc_output, enc_mask, coverage,
                            vvec, w_cov, focus);
    k6_epilogue<<<192, 256>>>(enc_mask, coverage, focus, out);
}

// round 14
// speedup vs baseline: 1.1892x; 1.0111x over previous
#include <cuda_runtime.h>

#define NB 16
#define SECL 16
#define WORDL 256
#define SLEN 4096
#define DIM 1024
#define FSZ 2
#define GATH (FSZ*WORDL)   // 512
#define NPART 64           // context partials (one per 8-row chunk)
#define KSPLIT 4           // k1 K-dimension split

// ---------------- scratch (device globals; no allocation) ----------------
__device__ float g_decpart[KSPLIT*NB*DIM];  // k1 partial dec features (bias in split 0)
__device__ float g_scores[NB*GATH];
__device__ float g_ctxpart[NPART*NB*DIM];   // 4 MB

__device__ __forceinline__ void pdl_wait() {
    asm volatile("griddepcontrol.wait;" ::: "memory");
}

// accurate tanh: 1 - 2/(e^{2x}+1), ex2/rcp MUFU (~1e-7 abs error)
__device__ __forceinline__ float fast_tanh(float x) {
    float e;
    asm("ex2.approx.f32 %0, %1;" : "=f"(e) : "f"(x * 2.8853900817779268f)); // 2*log2(e)
    float r;
    asm("rcp.approx.f32 %0, %1;" : "=f"(r) : "f"(e + 1.0f));
    return 1.0f - 2.0f * r;
}

// top-2 of focus[b] (jax first-occurrence tie rule); run by ONE thread
__device__ __forceinline__ void top2_focus(const float* __restrict__ focus, int b,
                                           int& i0, int& i1, float& v0, float& v1) {
    const float* f = focus + b*SECL;
    v0 = -__int_as_float(0x7f800000); i0 = 0;
#pragma unroll
    for (int j = 0; j < SECL; j++) { float x = __ldg(&f[j]); if (x > v0) { v0 = x; i0 = j; } }
    v1 = -__int_as_float(0x7f800000); i1 = 0;
#pragma unroll
    for (int j = 0; j < SECL; j++) {
        if (j == i0) continue;
        float x = __ldg(&f[j]); if (x > v1) { v1 = x; i1 = j; }
    }
}

// ---------------- K1: dec_feature partials, K split 4-way, merge-tree reduce ----------------
// grid 512 = 128 d-groups * 4 k-splits; warp owns 1 dim, 256 K-floats (2 float4/lane).
__global__ __launch_bounds__(256) void k1_decproj(const float* __restrict__ h,
                                                  const float* __restrict__ W,
                                                  const float* __restrict__ bvec) {
    int warp = threadIdx.x >> 5;
    int lane = threadIdx.x & 31;
    int dg = blockIdx.x >> 2;          // 0..127
    int ks = blockIdx.x & 3;           // 0..3
    int d  = dg*8 + warp;
    int k0 = ks*64;                    // float4 offset of this K quarter
    const float4* Wd = (const float4*)(W + (size_t)d*DIM) + k0 + lane;
    const float4* h4 = (const float4*)h + k0 + lane;
    float4 w0 = __ldg(Wd);
    float4 w1 = __ldg(Wd + 32);
    float acc[NB];
#pragma unroll
    for (int b = 0; b < NB; b++) {
        float4 a = __ldg(h4 + b*256);
        float4 c = __ldg(h4 + b*256 + 32);
        acc[b] = fmaf(w0.x,a.x, fmaf(w0.y,a.y, fmaf(w0.z,a.z, fmaf(w0.w,a.w,
                 fmaf(w1.x,c.x, fmaf(w1.y,c.y, fmaf(w1.z,c.z, w1.w*c.w)))))));
    }
    // merge-tree reduction: 16 accs -> 1 per lane (16 SHFL total)
#pragma unroll
    for (int i = 0; i < 8; i++) {
        float x = (lane & 16) ? acc[i] : acc[i+8];
        float y = __shfl_xor_sync(0xffffffffu, x, 16);
        acc[i] = ((lane & 16) ? acc[i+8] : acc[i]) + y;
    }
#pragma unroll
    for (int i = 0; i < 4; i++) {
        float x = (lane & 8) ? acc[i] : acc[i+4];
        float y = __shfl_xor_sync(0xffffffffu, x, 8);
        acc[i] = ((lane & 8) ? acc[i+4] : acc[i]) + y;
    }
#pragma unroll
    for (int i = 0; i < 2; i++) {
        float x = (lane & 4) ? acc[i] : acc[i+2];
        float y = __shfl_xor_sync(0xffffffffu, x, 4);
        acc[i] = ((lane & 4) ? acc[i+2] : acc[i]) + y;
    }
    {
        float x = (lane & 2) ? acc[0] : acc[1];
        float y = __shfl_xor_sync(0xffffffffu, x, 2);
        acc[0] = ((lane & 2) ? acc[1] : acc[0]) + y;
    }
    acc[0] += __shfl_xor_sync(0xffffffffu, acc[0], 1);
    // even lane holds full sum for batch b(lane)
    int b = ((lane >> 4) & 1)*8 + ((lane >> 3) & 1)*4 + ((lane >> 2) & 1)*2 + ((lane >> 1) & 1);
    if ((lane & 1) == 0) {
        float bd = (ks == 0) ? __ldg(&bvec[d]) : 0.f;
        g_decpart[(ks*NB + b)*DIM + d] = acc[0] + bd;
    }
}

// ---------------- K3 fused (PDL): scores + unnormalized weighted context partials ----------------
// 1024 blocks * 256 threads. Block = 8 consecutive rows of one (b, section-chunk).
// All k1-independent work (top2, mask/cov, enc_feature loads) runs BEFORE griddepcontrol.wait.
__global__ __launch_bounds__(256) void k3_fused(const float* __restrict__ enc_feature,
                                                const float* __restrict__ enc_output,
                                                const float* __restrict__ enc_mask,
                                                const float* __restrict__ coverage,
                                                const float* __restrict__ vvec,
                                                const float* __restrict__ w_cov,
                                                const float* __restrict__ focus) {
    __shared__ float sh_ps[8][8];   // [warp][row]
    __shared__ float sh_w[8];
    __shared__ float sh_m[8];
    __shared__ float sh_cov[8];
    __shared__ int   sh_sec;
    int id = blockIdx.x;
    int b  = id >> 6;
    int c  = id & 63;              // chunk within batch
    int f  = c >> 5;
    int w0 = (c & 31) * 8;         // word offset within section
    int warp = threadIdx.x >> 5;
    int lane = threadIdx.x & 31;
    if (threadIdx.x == 0) {
        int i0, i1; float v0, v1;
        top2_focus(focus, b, i0, i1, v0, v1);
        sh_sec = f ? i1 : i0;
    }
    __syncthreads();
    int srow = b*SLEN + sh_sec*WORDL + w0;     // global row index of row 0
    if (threadIdx.x < 8) {
        sh_m[threadIdx.x]   = enc_mask[srow + threadIdx.x];
        sh_cov[threadIdx.x] = coverage[srow + threadIdx.x];
    }
    __syncthreads();

    int sl = warp*32 + lane;                   // float4 index within dim
    const float4* efp = (const float4*)enc_feature + (size_t)srow*(DIM/4) + sl;
    float4 e0 = __ldg(efp + 0*(DIM/4));
    float4 e1 = __ldg(efp + 1*(DIM/4));
    float4 e2 = __ldg(efp + 2*(DIM/4));
    float4 e3 = __ldg(efp + 3*(DIM/4));
    float4 e4 = __ldg(efp + 4*(DIM/4));
    float4 e5 = __ldg(efp + 5*(DIM/4));
    float4 e6 = __ldg(efp + 6*(DIM/4));
    float4 e7 = __ldg(efp + 7*(DIM/4));
    float4 vv = __ldg((const float4*)vvec  + sl);
    float4 wc = __ldg((const float4*)w_cov + sl);

    // ---- everything above is independent of k1; now wait for g_decpart ----
    pdl_wait();

    // dec feature = sum of 4 K-split partials (bias folded into split 0)
    const float4* dp = (const float4*)g_decpart + b*(DIM/4) + sl;
    float4 d0 = dp[0*(NB*DIM/4)];
    float4 d1 = dp[1*(NB*DIM/4)];
    float4 d2 = dp[2*(NB*DIM/4)];
    float4 d3 = dp[3*(NB*DIM/4)];
    float4 dd = make_float4((d0.x+d1.x)+(d2.x+d3.x), (d0.y+d1.y)+(d2.y+d3.y),
                            (d0.z+d1.z)+(d2.z+d3.z), (d0.w+d1.w)+(d2.w+d3.w));
    float ps[8];
#define K3ROW(EV, R) { float cv = sh_cov[R]; \
        ps[R] = vv.x * fast_tanh(fmaf(cv, wc.x, EV.x + dd.x)) \
              + vv.y * fast_tanh(fmaf(cv, wc.y, EV.y + dd.y)) \
              + vv.z * fast_tanh(fmaf(cv, wc.z, EV.z + dd.z)) \
              + vv.w * fast_tanh(fmaf(cv, wc.w, EV.w + dd.w)); }
    K3ROW(e0, 0) K3ROW(e1, 1) K3ROW(e2, 2) K3ROW(e3, 3)
    K3ROW(e4, 4) K3ROW(e5, 5) K3ROW(e6, 6) K3ROW(e7, 7)
#undef K3ROW
#pragma unroll
    for (int r = 0; r < 8; r++) {
#pragma unroll
        for (int o = 16; o > 0; o >>= 1)
            ps[r] += __shfl_xor_sync(0xffffffffu, ps[r], o);
    }
    if (lane == 0) {
#pragma unroll
        for (int r = 0; r < 8; r++) sh_ps[warp][r] = ps[r];
    }
    __syncthreads();
    if (threadIdx.x < 8) {
        int r = threadIdx.x;
        float sc = ((sh_ps[0][r] + sh_ps[1][r]) + (sh_ps[2][r] + sh_ps[3][r]))
                 + ((sh_ps[4][r] + sh_ps[5][r]) + (sh_ps[6][r] + sh_ps[7][r]));
        g_scores[b*GATH + f*WORDL + w0 + r] = sc;
        sh_w[r] = __expf(sc) * sh_m[r];        // unnormalized weight
    }
    __syncthreads();

    const float4* eop = (const float4*)enc_output + (size_t)srow*(DIM/4) + sl;
    float4 r0 = __ldg(eop + 0*(DIM/4));
    float4 r1 = __ldg(eop + 1*(DIM/4));
    float4 r2 = __ldg(eop + 2*(DIM/4));
    float4 r3 = __ldg(eop + 3*(DIM/4));
    float4 r4 = __ldg(eop + 4*(DIM/4));
    float4 r5 = __ldg(eop + 5*(DIM/4));
    float4 r6 = __ldg(eop + 6*(DIM/4));
    float4 r7 = __ldg(eop + 7*(DIM/4));
    float c0 = sh_w[0], c1 = sh_w[1], c2 = sh_w[2], c3 = sh_w[3];
    float c4 = sh_w[4], c5 = sh_w[5], c6 = sh_w[6], c7 = sh_w[7];
    float4 s;
    s.x = (fmaf(c0,r0.x, c1*r1.x) + fmaf(c2,r2.x, c3*r3.x))
        + (fmaf(c4,r4.x, c5*r5.x) + fmaf(c6,r6.x, c7*r7.x));
    s.y = (fmaf(c0,r0.y, c1*r1.y) + fmaf(c2,r2.y, c3*r3.y))
        + (fmaf(c4,r4.y, c5*r5.y) + fmaf(c6,r6.y, c7*r7.y));
    s.z = (fmaf(c0,r0.z, c1*r1.z) + fmaf(c2,r2.z, c3*r3.z))
        + (fmaf(c4,r4.z, c5*r5.z) + fmaf(c6,r6.z, c7*r7.z));
    s.w = (fmaf(c0,r0.w, c1*r1.w) + fmaf(c2,r2.w, c3*r3.w))
        + (fmaf(c4,r4.w, c5*r5.w) + fmaf(c6,r6.w, c7*r7.w));
    *((float4*)(g_ctxpart + ((size_t)(c*NB + b))*DIM) + sl) = s;
}

// ---------------- block reduce (256 threads, 8 warps) ----------------
__device__ __forceinline__ float blkred256(float v, float* red, bool is_max) {
#pragma unroll
    for (int o = 16; o > 0; o >>= 1) {
        float t = __shfl_xor_sync(0xffffffffu, v, o);
        v = is_max ? fmaxf(v, t) : (v + t);
    }
    __syncthreads();
    if ((threadIdx.x & 31) == 0) red[threadIdx.x >> 5] = v;
    __syncthreads();
    if (threadIdx.x < 32) {
        float x = (threadIdx.x < 8) ? red[threadIdx.x]
                                    : (is_max ? -__int_as_float(0x7f800000) : 0.f);
#pragma unroll
        for (int o = 4; o > 0; o >>= 1) {
            float t = __shfl_xor_sync(0xffffffffu, x, o);
            x = is_max ? fmaxf(x, t) : (x + t);
        }
        if (threadIdx.x == 0) red[0] = x;
    }
    __syncthreads();
    return red[0];
}

// ---------------- K6 (PDL): softmax recompute + scaled combine + scatter ----------------
__global__ __launch_bounds__(256) void k6_epilogue(const float* __restrict__ enc_mask,
                                                   const float* __restrict__ coverage,
                                                   const float* __restrict__ focus,
                                                   float* __restrict__ out) {
    __shared__ float red[8];
    __shared__ int   sh_i[2];
    __shared__ float sh_v[2];
    bool is_comb = blockIdx.x < 128;
    int b = is_comb ? (blockIdx.x >> 3) : ((blockIdx.x - 128) >> 2);
    int tid = threadIdx.x;
    if (tid == 0) {
        int i0, i1; float v0, v1;
        top2_focus(focus, b, i0, i1, v0, v1);
        sh_i[0] = i0; sh_i[1] = i1; sh_v[0] = v0; sh_v[1] = v1;
    }
    __syncthreads();
    int i0 = sh_i[0], i1 = sh_i[1];
    float v0 = sh_v[0], v1 = sh_v[1];
    float m0  = __ldg(&enc_mask[b*SLEN + i0*WORDL + tid]);
    float m1  = __ldg(&enc_mask[b*SLEN + i1*WORDL + tid]);

    // ---- wait for k3's g_scores/g_ctxpart ----
    pdl_wait();

    float sc0 = g_scores[b*GATH + tid];
    float sc1 = g_scores[b*GATH + WORDL + tid];
    float mx  = blkred256(fmaxf(sc0, sc1), red, true);
    float e0  = __expf(sc0 - mx) * m0;
    float e1  = __expf(sc1 - mx) * m1;
    float S   = blkred256(fmaf(v0, e0, v1*e1), red, false);

    if (is_comb) {
        __shared__ float4 shc[8][32];
        float emx = __expf(-mx);
        float scale0 = v0 * emx / S;
        float scale1 = v1 * emx / S;
        int o = tid & 31;
        int g = tid >> 5;
        int i = b*256 + (blockIdx.x & 7)*32 + o;
        const float4* cp = (const float4*)g_ctxpart + i;
        float4 t0 = cp[(size_t)(g*8 + 0)*(NB*DIM/4)];
        float4 t1 = cp[(size_t)(g*8 + 1)*(NB*DIM/4)];
        float4 t2 = cp[(size_t)(g*8 + 2)*(NB*DIM/4)];
        float4 t3 = cp[(size_t)(g*8 + 3)*(NB*DIM/4)];
        float4 t4 = cp[(size_t)(g*8 + 4)*(NB*DIM/4)];
        float4 t5 = cp[(size_t)(g*8 + 5)*(NB*DIM/4)];
        float4 t6 = cp[(size_t)(g*8 + 6)*(NB*DIM/4)];
        float4 t7 = cp[(size_t)(g*8 + 7)*(NB*DIM/4)];
        float sc = (g < 4) ? scale0 : scale1;
        shc[g][o] = make_float4(
            sc*(((t0.x+t1.x)+(t2.x+t3.x)) + ((t4.x+t5.x)+(t6.x+t7.x))),
            sc*(((t0.y+t1.y)+(t2.y+t3.y)) + ((t4.y+t5.y)+(t6.y+t7.y))),
            sc*(((t0.z+t1.z)+(t2.z+t3.z)) + ((t4.z+t5.z)+(t6.z+t7.z))),
            sc*(((t0.w+t1.w)+(t2.w+t3.w)) + ((t4.w+t5.w)+(t6.w+t7.w))));
        __syncthreads();
        if (tid < 32) {
            float4 a = shc[0][tid], b4 = shc[1][tid], c4 = shc[2][tid], d4 = shc[3][tid];
            float4 e4 = shc[4][tid], f4 = shc[5][tid], g4 = shc[6][tid], h4 = shc[7][tid];
            int ii = b*256 + (blockIdx.x & 7)*32 + tid;
            ((float4*)out)[ii] = make_float4(
                ((a.x+b4.x)+(c4.x+d4.x)) + ((e4.x+f4.x)+(g4.x+h4.x)),
                ((a.y+b4.y)+(c4.y+d4.y)) + ((e4.y+f4.y)+(g4.y+h4.y)),
                ((a.z+b4.z)+(c4.z+d4.z)) + ((e4.z+f4.z)+(g4.z+h4.z)),
                ((a.w+b4.w)+(c4.w+d4.w)) + ((e4.w+f4.w)+(g4.w+h4.w)));
        }
    } else {
        int gb = blockIdx.x - 128;
        int p4 = (gb & 3)*256 + tid;
        int pos = p4 << 2;
        int si = pos >> 8;
        int w  = pos & 255;
        float4 av = make_float4(0.f, 0.f, 0.f, 0.f);
        float4 m4 = __ldg((const float4*)(enc_mask + b*SLEN) + p4);
        if (si == i0) {
            float4 s4 = *(const float4*)(g_scores + b*GATH + w);
            float k = v0 / S;
            av = make_float4(k*__expf(s4.x - mx)*m4.x, k*__expf(s4.y - mx)*m4.y,
                             k*__expf(s4.z - mx)*m4.z, k*__expf(s4.w - mx)*m4.w);
        } else if (si == i1) {
            float4 s4 = *(const float4*)(g_scores + b*GATH + WORDL + w);
            float k = v1 / S;
            av = make_float4(k*__expf(s4.x - mx)*m4.x, k*__expf(s4.y - mx)*m4.y,
                             k*__expf(s4.z - mx)*m4.z, k*__expf(s4.w - mx)*m4.w);
        }
        float4 cv = __ldg((const float4*)(coverage + b*SLEN) + p4);
        float4* oa = (float4*)(out + NB*DIM + b*SLEN);
        float4* oc = (float4*)(out + NB*DIM + NB*SLEN + b*SLEN);
        oa[p4] = av;
        oc[p4] = make_float4(cv.x + av.x, cv.y + av.y, cv.z + av.z, cv.w + av.w);
    }
}

extern "C" void kernel_launch(void* const* d_in, const int* in_sizes, int n_in,
                              void* d_out, int out_size) {
    const float* dec_hidden  = (const float*)d_in[0];
    const float* enc_output  = (const float*)d_in[1];
    const float* enc_feature = (const float*)d_in[2];
    const float* enc_mask    = (const float*)d_in[3];
    // d_in[4] = sec_attn (unused by reference)
    const float* coverage    = (const float*)d_in[5];
    const float* focus       = (const float*)d_in[6];
    const float* W_dec       = (const float*)d_in[7];
    const float* b_dec       = (const float*)d_in[8];
    const float* vvec        = (const float*)d_in[9];
    const float* w_cov       = (const float*)d_in[10];
    float* out = (float*)d_out;

    k1_decproj<<<512, 256>>>(dec_hidden, W_dec, b_dec);

    // k3 with programmatic dependent launch (overlaps its prologue with k1)
    {
        cudaLaunchConfig_t cfg = {};
        cfg.gridDim  = dim3(1024, 1, 1);
        cfg.blockDim = dim3(256, 1, 1);
        cfg.stream   = 0;
        cudaLaunchAttribute attr[1];
        attr[0].id = cudaLaunchAttributeProgrammaticStreamSerialization;
        attr[0].val.programmaticStreamSerializationAllowed = 1;
        cfg.attrs = attr;
        cfg.numAttrs = 1;
        cudaLaunchKernelEx(&cfg, k3_fused, enc_feature, enc_output, enc_mask,
                           coverage, vvec, w_cov, focus);
    }

    // k6 with PDL (overlaps its prologue with k3's tail)
    {
        cudaLaunchConfig_t cfg = {};
        cfg.gridDim  = dim3(192, 1, 1);
        cfg.blockDim = dim3(256, 1, 1);
        cfg.stream   = 0;
        cudaLaunchAttribute attr[1];
        attr[0].id = cudaLaunchAttributeProgrammaticStreamSerialization;
        attr[0].val.programmaticStreamSerializationAllowed = 1;
        cfg.attrs = attr;
        cfg.numAttrs = 1;
        cudaLaunchKernelEx(&cfg, k6_epilogue, enc_mask, coverage, focus, out);
    }
}